// round 16
// baseline (speedup 1.0000x reference)
#include <cuda_runtime.h>
#include <cuda_bf16.h>
#include <math.h>
#include <stdint.h>

#define B_     16
#define C_     512
#define N_     1024
#define HEADS  8
#define CH     64
#define GROUPS 32
#define CPG    16

#define QKVW_ELEMS (3 * C_ * C_)
#define PROJW_ELEMS (C_ * C_)

// ---------------- scratch (NEVER passed as host-side kernel args) ----------------
__device__ float g_xn [B_ * C_ * N_];             // GN out fp32 ch-major
__device__ __nv_bfloat16 g_wh[QKVW_ELEMS + PROJW_ELEMS];
__device__ __nv_bfloat16 g_wl[QKVW_ELEMS + PROJW_ELEMS];
__device__ __nv_bfloat16 g_xh[B_ * N_ * C_];      // GN token-major hi/lo
__device__ __nv_bfloat16 g_xl[B_ * N_ * C_];
__device__ __nv_bfloat16 g_qh[B_ * N_ * C_];      // Q token-major (bias+scale applied)
__device__ __nv_bfloat16 g_ql[B_ * N_ * C_];
__device__ __nv_bfloat16 g_kh[B_ * N_ * C_];      // K token-major
__device__ __nv_bfloat16 g_kl[B_ * N_ * C_];
__device__ __nv_bfloat16 g_vh[B_ * C_ * N_];      // V ch-major
__device__ __nv_bfloat16 g_vl[B_ * C_ * N_];
__device__ __nv_bfloat16 g_ah[B_ * N_ * C_];      // attn out token-major
__device__ __nv_bfloat16 g_al[B_ * N_ * C_];

// ---------------- helpers ----------------
__device__ __forceinline__ void mma_bf16(float* d, const uint32_t* a, const uint32_t* b) {
    asm volatile("mma.sync.aligned.m16n8k16.row.col.f32.bf16.bf16.f32 "
                 "{%0,%1,%2,%3}, {%4,%5,%6,%7}, {%8,%9}, {%0,%1,%2,%3};"
                 : "+f"(d[0]), "+f"(d[1]), "+f"(d[2]), "+f"(d[3])
                 : "r"(a[0]), "r"(a[1]), "r"(a[2]), "r"(a[3]), "r"(b[0]), "r"(b[1]));
}
__device__ __forceinline__ void split_bf(float v, __nv_bfloat16& h, __nv_bfloat16& l) {
    uint32_t u  = __float_as_uint(v);
    uint32_t hb = (u + 0x8000u) & 0xFFFF0000u;
    h = __ushort_as_bfloat16((unsigned short)(hb >> 16));
    float r = v - __uint_as_float(hb);
    uint32_t lb = (__float_as_uint(r) + 0x8000u) & 0xFFFF0000u;
    l = __ushort_as_bfloat16((unsigned short)(lb >> 16));
}
__device__ __forceinline__ void split2(float x, float y, uint32_t& hi, uint32_t& lo) {
    __nv_bfloat16 hx, lx, hy, ly;
    split_bf(x, hx, lx); split_bf(y, hy, ly);
    hi = (uint32_t)__bfloat16_as_ushort(hx) | ((uint32_t)__bfloat16_as_ushort(hy) << 16);
    lo = (uint32_t)__bfloat16_as_ushort(lx) | ((uint32_t)__bfloat16_as_ushort(ly) << 16);
}
__device__ __forceinline__ uint32_t smem_u32(const void* p) {
    uint32_t a;
    asm("{ .reg .u64 t; cvta.to.shared.u64 t, %1; cvt.u32.u64 %0, t; }" : "=r"(a) : "l"(p));
    return a;
}
__device__ __forceinline__ void cp_async16(uint32_t saddr, const void* g) {
    asm volatile("cp.async.ca.shared.global [%0], [%1], 16;" :: "r"(saddr), "l"(g));
}
#define CP_COMMIT() asm volatile("cp.async.commit_group;")
#define CP_WAIT0()  asm volatile("cp.async.wait_group 0;" ::: "memory")

// ======================================================================
// 1) GroupNorm -> g_xn fp32 ch-major (proven)
// ======================================================================
__global__ __launch_bounds__(256)
void groupnorm_kernel(const float* __restrict__ x,
                      const float* __restrict__ w,
                      const float* __restrict__ bias)
{
    const int batch = blockIdx.x >> 5;
    const int g     = blockIdx.x & 31;
    const float* xp = x    + ((size_t)batch * C_ + g * CPG) * N_;
    float*       op = g_xn + ((size_t)batch * C_ + g * CPG) * N_;
    const int NE = CPG * N_;

    float s = 0.f, s2 = 0.f;
    const float4* xp4 = (const float4*)xp;
    for (int i = threadIdx.x; i < NE / 4; i += 256) {
        float4 v = xp4[i];
        s  += v.x + v.y + v.z + v.w;
        s2 += v.x * v.x + v.y * v.y + v.z * v.z + v.w * v.w;
    }
    __shared__ float rs[8], rs2[8];
    #pragma unroll
    for (int o = 16; o > 0; o >>= 1) {
        s  += __shfl_down_sync(0xffffffffu, s,  o);
        s2 += __shfl_down_sync(0xffffffffu, s2, o);
    }
    const int wid = threadIdx.x >> 5, lane = threadIdx.x & 31;
    if (lane == 0) { rs[wid] = s; rs2[wid] = s2; }
    __syncthreads();
    if (wid == 0) {
        s  = (lane < 8) ? rs[lane]  : 0.f;
        s2 = (lane < 8) ? rs2[lane] : 0.f;
        #pragma unroll
        for (int o = 4; o > 0; o >>= 1) {
            s  += __shfl_down_sync(0xffffffffu, s,  o);
            s2 += __shfl_down_sync(0xffffffffu, s2, o);
        }
        if (lane == 0) { rs[0] = s; rs2[0] = s2; }
    }
    __syncthreads();
    const float mean = rs[0] * (1.f / NE);
    const float var  = rs2[0] * (1.f / NE) - mean * mean;
    const float inv  = rsqrtf(var + 1e-5f);
    for (int i = threadIdx.x; i < NE; i += 256) {
        int ch = g * CPG + (i >> 10);
        op[i] = (xp[i] - mean) * inv * w[ch] + bias[ch];
    }
}

// ======================================================================
// weight split + GN transpose-split
// ======================================================================
__global__ __launch_bounds__(256)
void split_w_kernel(const float* __restrict__ qw, const float* __restrict__ pw)
{
    int i = blockIdx.x * 256 + threadIdx.x;
    if (i >= QKVW_ELEMS + PROJW_ELEMS) return;
    float v = (i < QKVW_ELEMS) ? qw[i] : pw[i - QKVW_ELEMS];
    __nv_bfloat16 h, l; split_bf(v, h, l);
    g_wh[i] = h; g_wl[i] = l;
}

__global__ __launch_bounds__(256)
void transX_kernel()
{
    __shared__ float sm[32][33];
    const int b    = blockIdx.z;
    const int tok0 = blockIdx.x * 32;
    const int ch0  = blockIdx.y * 32;
    const int tid  = threadIdx.x;
    {
        const int row = tid >> 3;
        const int c4  = (tid & 7) * 4;
        float4 v = *(const float4*)(g_xn + (size_t)b * C_ * N_ +
                                    (size_t)(ch0 + row) * N_ + tok0 + c4);
        sm[row][c4 + 0] = v.x; sm[row][c4 + 1] = v.y;
        sm[row][c4 + 2] = v.z; sm[row][c4 + 3] = v.w;
    }
    __syncthreads();
    {
        const int trow = tid >> 3;
        const int cc   = (tid & 7) * 4;
        uint32_t h01, l01, h23, l23;
        split2(sm[cc + 0][trow], sm[cc + 1][trow], h01, l01);
        split2(sm[cc + 2][trow], sm[cc + 3][trow], h23, l23);
        const size_t o = ((size_t)(b * N_ + tok0 + trow)) * C_ + ch0 + cc;
        *(uint2*)(g_xh + o) = make_uint2(h01, h23);
        *(uint2*)(g_xl + o) = make_uint2(l01, l23);
    }
}

// ======================================================================
// double-buffered cp.async bf16x3 GEMM mainloop (verified combo-0 layout)
// ======================================================================
#define ROWW        36
#define TILE_WORDS  (128 * ROWW)
#define GEMM_SMEM_SZ (8 * TILE_WORDS * 4)   // 2 buffers x 4 tiles = 147456 B

__device__ __forceinline__
void gemm_mainloop(uint32_t* smw,
                   const __nv_bfloat16* __restrict__ a_h, const __nv_bfloat16* __restrict__ a_l,
                   const __nv_bfloat16* __restrict__ b_h, const __nv_bfloat16* __restrict__ b_l,
                   float acc[4][4][4])
{
    const uint32_t sbase = smem_u32(smw);
    const int tid = threadIdx.x;
    const int wid = tid >> 5, lane = tid & 31;
    const int wm = wid & 1, wn = wid >> 1;
    const int gid = lane >> 2, tig = lane & 3;

    // issue loads for chunk kc into buffer (kc&1)
    auto issue = [&](int kc) {
        const int k0 = kc * 64;
        const int bufw = (kc & 1) * 4 * TILE_WORDS;
        #pragma unroll
        for (int t = 0; t < 4; t++) {
            const int idx = tid + t * 256;
            const int row = idx >> 3, cc = idx & 7;
            const size_t gofs = (size_t)row * C_ + k0 + cc * 8;
            const uint32_t so = sbase + (bufw + row * ROWW + cc * 4) * 4;
            cp_async16(so,                       a_h + gofs);
            cp_async16(so + TILE_WORDS * 4,      a_l + gofs);
            cp_async16(so + 2 * TILE_WORDS * 4,  b_h + gofs);
            cp_async16(so + 3 * TILE_WORDS * 4,  b_l + gofs);
        }
        CP_COMMIT();
    };

    issue(0);
    for (int kc = 0; kc < 8; kc++) {
        CP_WAIT0();
        __syncthreads();
        if (kc < 7) issue(kc + 1);
        const int bufw = (kc & 1) * 4 * TILE_WORDS;
        uint32_t* Asmh = smw + bufw;
        uint32_t* Asml = Asmh + TILE_WORDS;
        uint32_t* Bsmh = Asml + TILE_WORDS;
        uint32_t* Bsml = Bsmh + TILE_WORDS;

        #pragma unroll
        for (int ks = 0; ks < 4; ks++) {
            const int kw = ks * 8 + tig;
            uint32_t ah[4][4], al[4][4], bh[4][2], bl[4][2];
            #pragma unroll
            for (int mi = 0; mi < 4; mi++) {
                const int r0 = (wm * 64 + mi * 16 + gid) * ROWW + kw;
                const int r1 = r0 + 8 * ROWW;
                ah[mi][0] = Asmh[r0];     ah[mi][1] = Asmh[r1];
                ah[mi][2] = Asmh[r0 + 4]; ah[mi][3] = Asmh[r1 + 4];
                al[mi][0] = Asml[r0];     al[mi][1] = Asml[r1];
                al[mi][2] = Asml[r0 + 4]; al[mi][3] = Asml[r1 + 4];
            }
            #pragma unroll
            for (int ni = 0; ni < 4; ni++) {
                const int rb = (wn * 32 + ni * 8 + gid) * ROWW + kw;
                bh[ni][0] = Bsmh[rb]; bh[ni][1] = Bsmh[rb + 4];
                bl[ni][0] = Bsml[rb]; bl[ni][1] = Bsml[rb + 4];
            }
            #pragma unroll
            for (int mi = 0; mi < 4; mi++)
                #pragma unroll
                for (int ni = 0; ni < 4; ni++) {
                    mma_bf16(acc[mi][ni], ah[mi], bh[ni]);
                    mma_bf16(acc[mi][ni], al[mi], bh[ni]);
                    mma_bf16(acc[mi][ni], ah[mi], bl[ni]);
                }
        }
        __syncthreads();
    }
}

// QKV GEMM with fused Q/K/V output conversion
__global__ __launch_bounds__(256)
void qkv_tc_kernel(const float* __restrict__ bias)
{
    extern __shared__ uint32_t smw[];
    const int tid = threadIdx.x;
    const int wid = tid >> 5, lane = tid & 31;
    const int wm = wid & 1, wn = wid >> 1;
    const int gid = lane >> 2, tig = lane & 3;
    const int bN = blockIdx.x * 128;     // token base
    const int bM = blockIdx.y * 128;     // channel base (0..1535)
    const int b  = blockIdx.z;

    float acc[4][4][4];
    #pragma unroll
    for (int i = 0; i < 4; i++)
        #pragma unroll
        for (int j = 0; j < 4; j++)
            #pragma unroll
            for (int k = 0; k < 4; k++) acc[i][j][k] = 0.f;

    gemm_mainloop(smw,
                  g_wh + (size_t)bM * C_, g_wl + (size_t)bM * C_,
                  g_xh + ((size_t)b * N_ + bN) * C_, g_xl + ((size_t)b * N_ + bN) * C_,
                  acc);

    if (bM < 1024) {
        // Q or K: token-major output, Q scaled by 0.125 (after bias)
        const bool isQ = bM < 512;
        __nv_bfloat16* dh = isQ ? g_qh : g_kh;
        __nv_bfloat16* dl = isQ ? g_ql : g_kl;
        const int chBase = isQ ? bM : bM - 512;
        const float scale = isQ ? 0.125f : 1.f;
        #pragma unroll
        for (int mi = 0; mi < 4; mi++) {
            #pragma unroll
            for (int half = 0; half < 2; half++) {
                const int rrel = wm * 64 + mi * 16 + half * 8 + gid;
                const int ch = chBase + rrel;
                const float bs = bias[bM + rrel];
                #pragma unroll
                for (int ni = 0; ni < 4; ni++) {
                    const int tok = bN + wn * 32 + ni * 8 + tig * 2;
                    const float v0 = (acc[mi][ni][half * 2 + 0] + bs) * scale;
                    const float v1 = (acc[mi][ni][half * 2 + 1] + bs) * scale;
                    __nv_bfloat16 h0, l0, h1, l1;
                    split_bf(v0, h0, l0);
                    split_bf(v1, h1, l1);
                    const size_t o0 = ((size_t)(b * N_ + tok)) * C_ + ch;
                    dh[o0] = h0;       dl[o0] = l0;
                    dh[o0 + C_] = h1;  dl[o0 + C_] = l1;
                }
            }
        }
    } else {
        // V: ch-major output
        const int chBase = bM - 1024;
        #pragma unroll
        for (int mi = 0; mi < 4; mi++) {
            #pragma unroll
            for (int half = 0; half < 2; half++) {
                const int rrel = wm * 64 + mi * 16 + half * 8 + gid;
                const float bs = bias[bM + rrel];
                const size_t rb = ((size_t)(b * C_ + chBase + rrel)) * N_;
                #pragma unroll
                for (int ni = 0; ni < 4; ni++) {
                    const int tok = bN + wn * 32 + ni * 8 + tig * 2;
                    uint32_t hi, lo;
                    split2(acc[mi][ni][half * 2 + 0] + bs,
                           acc[mi][ni][half * 2 + 1] + bs, hi, lo);
                    *(uint32_t*)(g_vh + rb + tok) = hi;
                    *(uint32_t*)(g_vl + rb + tok) = lo;
                }
            }
        }
    }
}

// proj GEMM: fp32 out + bias + residual
__global__ __launch_bounds__(256)
void proj_tc_kernel(const float* __restrict__ bias, const float* __restrict__ x,
                    float* __restrict__ out)
{
    extern __shared__ uint32_t smw[];
    const int tid = threadIdx.x;
    const int wid = tid >> 5, lane = tid & 31;
    const int wm = wid & 1, wn = wid >> 1;
    const int gid = lane >> 2, tig = lane & 3;
    const int bN = blockIdx.x * 128;
    const int bM = blockIdx.y * 128;
    const int b  = blockIdx.z;

    float acc[4][4][4];
    #pragma unroll
    for (int i = 0; i < 4; i++)
        #pragma unroll
        for (int j = 0; j < 4; j++)
            #pragma unroll
            for (int k = 0; k < 4; k++) acc[i][j][k] = 0.f;

    gemm_mainloop(smw,
                  g_wh + QKVW_ELEMS + (size_t)bM * C_, g_wl + QKVW_ELEMS + (size_t)bM * C_,
                  g_ah + ((size_t)b * N_ + bN) * C_, g_al + ((size_t)b * N_ + bN) * C_,
                  acc);

    const int tc = tig * 2;
    #pragma unroll
    for (int mi = 0; mi < 4; mi++) {
        #pragma unroll
        for (int half = 0; half < 2; half++) {
            const int row = bM + wm * 64 + mi * 16 + half * 8 + gid;
            const float bs = bias[row];
            float* outp = out + ((size_t)b * C_ + row) * N_ + bN;
            const float* rp = x + ((size_t)b * C_ + row) * N_ + bN;
            #pragma unroll
            for (int ni = 0; ni < 4; ni++) {
                const int col = wn * 32 + ni * 8 + tc;
                float2 r = *(const float2*)(rp + col);
                float2 v;
                v.x = acc[mi][ni][half * 2 + 0] + bs + r.x;
                v.y = acc[mi][ni][half * 2 + 1] + bs + r.y;
                *(float2*)(outp + col) = v;
            }
        }
    }
}

// ======================================================================
// flash attention via mma.sync bf16x3 — 128 threads, qtile 64, 3 CTAs/SM
// ======================================================================
#define AROWW 36
#define VROWW 68
#define ATT_SMEM ((2 * 128 * AROWW + 2 * 64 * VROWW) * 4)   // 71680 B

__global__ __launch_bounds__(128, 3)
void attn_mma_kernel()
{
    extern __shared__ uint32_t sm[];
    uint32_t* Kh = sm;
    uint32_t* Kl = Kh + 128 * AROWW;
    uint32_t* Vh = Kl + 128 * AROWW;
    uint32_t* Vl = Vh + 64 * VROWW;

    const int b  = blockIdx.z;
    const int h  = blockIdx.y;
    const int qt = blockIdx.x;
    const int tid = threadIdx.x, wid = tid >> 5, lane = tid & 31;
    const int g = lane >> 2, t = lane & 3;

    const int qrow0 = qt * 64 + wid * 16;

    uint32_t Qh[4][4], Ql[4][4];
    {
        const __nv_bfloat16* qh0 = g_qh + ((size_t)(b * N_ + qrow0)) * C_ + h * CH;
        const __nv_bfloat16* ql0 = g_ql + ((size_t)(b * N_ + qrow0)) * C_ + h * CH;
        #pragma unroll
        for (int ks = 0; ks < 4; ks++) {
            const int k = ks * 16 + 2 * t;
            Qh[ks][0] = *(const uint32_t*)(qh0 + (size_t)g * C_ + k);
            Qh[ks][1] = *(const uint32_t*)(qh0 + (size_t)(g + 8) * C_ + k);
            Qh[ks][2] = *(const uint32_t*)(qh0 + (size_t)g * C_ + k + 8);
            Qh[ks][3] = *(const uint32_t*)(qh0 + (size_t)(g + 8) * C_ + k + 8);
            Ql[ks][0] = *(const uint32_t*)(ql0 + (size_t)g * C_ + k);
            Ql[ks][1] = *(const uint32_t*)(ql0 + (size_t)(g + 8) * C_ + k);
            Ql[ks][2] = *(const uint32_t*)(ql0 + (size_t)g * C_ + k + 8);
            Ql[ks][3] = *(const uint32_t*)(ql0 + (size_t)(g + 8) * C_ + k + 8);
        }
    }

    float accO[8][4];
    #pragma unroll
    for (int i = 0; i < 8; i++)
        #pragma unroll
        for (int j = 0; j < 4; j++) accO[i][j] = 0.f;
    float mrow[2] = { -INFINITY, -INFINITY };
    float lrow[2] = { 0.f, 0.f };

    for (int kt = 0; kt < 8; kt++) {
        const int ktok0 = kt * 128;
        #pragma unroll
        for (int t8 = 0; t8 < 8; t8++) {
            const int idx = tid + t8 * 128;
            const int row = idx >> 3, cc = idx & 7;
            const size_t so = ((size_t)(b * N_ + ktok0 + row)) * C_ + h * CH + cc * 8;
            *(uint4*)&Kh[row * AROWW + cc * 4] = *(const uint4*)(g_kh + so);
            *(uint4*)&Kl[row * AROWW + cc * 4] = *(const uint4*)(g_kl + so);
        }
        #pragma unroll
        for (int t8 = 0; t8 < 8; t8++) {
            const int idx = tid + t8 * 128;
            const int row = idx >> 4, cc = idx & 15;
            const size_t so = ((size_t)(b * C_ + h * CH + row)) * N_ + ktok0 + cc * 8;
            *(uint4*)&Vh[row * VROWW + cc * 4] = *(const uint4*)(g_vh + so);
            *(uint4*)&Vl[row * VROWW + cc * 4] = *(const uint4*)(g_vl + so);
        }
        __syncthreads();

        float accS[16][4];
        #pragma unroll
        for (int i = 0; i < 16; i++)
            #pragma unroll
            for (int j = 0; j < 4; j++) accS[i][j] = 0.f;
        #pragma unroll
        for (int ks = 0; ks < 4; ks++) {
            const int kw = ks * 8 + t;
            #pragma unroll
            for (int ni = 0; ni < 16; ni++) {
                const int rb = (ni * 8 + g) * AROWW + kw;
                uint32_t bh[2] = { Kh[rb], Kh[rb + 4] };
                uint32_t bl[2] = { Kl[rb], Kl[rb + 4] };
                mma_bf16(accS[ni], Qh[ks], bh);
                mma_bf16(accS[ni], Ql[ks], bh);
                mma_bf16(accS[ni], Qh[ks], bl);
            }
        }

        #pragma unroll
        for (int r = 0; r < 2; r++) {
            float mx = mrow[r];
            #pragma unroll
            for (int ni = 0; ni < 16; ni++) {
                mx = fmaxf(mx, accS[ni][r * 2 + 0]);
                mx = fmaxf(mx, accS[ni][r * 2 + 1]);
            }
            mx = fmaxf(mx, __shfl_xor_sync(0xffffffffu, mx, 1));
            mx = fmaxf(mx, __shfl_xor_sync(0xffffffffu, mx, 2));
            const float corr = __expf(mrow[r] - mx);
            mrow[r] = mx;
            float sum = 0.f;
            #pragma unroll
            for (int ni = 0; ni < 16; ni++) {
                float p0 = __expf(accS[ni][r * 2 + 0] - mx);
                float p1 = __expf(accS[ni][r * 2 + 1] - mx);
                accS[ni][r * 2 + 0] = p0;
                accS[ni][r * 2 + 1] = p1;
                sum += p0 + p1;
            }
            sum += __shfl_xor_sync(0xffffffffu, sum, 1);
            sum += __shfl_xor_sync(0xffffffffu, sum, 2);
            lrow[r] = lrow[r] * corr + sum;
            #pragma unroll
            for (int ni = 0; ni < 8; ni++) {
                accO[ni][r * 2 + 0] *= corr;
                accO[ni][r * 2 + 1] *= corr;
            }
        }

        #pragma unroll
        for (int ks = 0; ks < 8; ks++) {
            uint32_t ph[4], pl[4];
            split2(accS[2 * ks][0],     accS[2 * ks][1],     ph[0], pl[0]);
            split2(accS[2 * ks][2],     accS[2 * ks][3],     ph[1], pl[1]);
            split2(accS[2 * ks + 1][0], accS[2 * ks + 1][1], ph[2], pl[2]);
            split2(accS[2 * ks + 1][2], accS[2 * ks + 1][3], ph[3], pl[3]);
            #pragma unroll
            for (int ni = 0; ni < 8; ni++) {
                const int rbv = (ni * 8 + g) * VROWW + ks * 8 + t;
                uint32_t bh[2] = { Vh[rbv], Vh[rbv + 4] };
                uint32_t bl[2] = { Vl[rbv], Vl[rbv + 4] };
                mma_bf16(accO[ni], ph, bh);
                mma_bf16(accO[ni], pl, bh);
                mma_bf16(accO[ni], ph, bl);
            }
        }
        __syncthreads();
    }

    const float inv0 = 1.f / lrow[0];
    const float inv1 = 1.f / lrow[1];
    #pragma unroll
    for (int r = 0; r < 2; r++) {
        const float inv = r ? inv1 : inv0;
        const size_t ob = ((size_t)(b * N_ + qrow0 + g + r * 8)) * C_ + h * CH + 2 * t;
        #pragma unroll
        for (int ni = 0; ni < 8; ni++) {
            uint32_t hi, lo;
            split2(accO[ni][r * 2 + 0] * inv, accO[ni][r * 2 + 1] * inv, hi, lo);
            *(uint32_t*)(g_ah + ob + ni * 8) = hi;
            *(uint32_t*)(g_al + ob + ni * 8) = lo;
        }
    }
}

// ======================================================================
// launch
// ======================================================================
extern "C" void kernel_launch(void* const* d_in, const int* in_sizes, int n_in,
                              void* d_out, int out_size)
{
    const float* x      = (const float*)d_in[0];
    const float* norm_w = (const float*)d_in[1];
    const float* norm_b = (const float*)d_in[2];
    const float* qkv_w  = (const float*)d_in[3];
    const float* qkv_b  = (const float*)d_in[4];
    const float* proj_w = (const float*)d_in[5];
    const float* proj_b = (const float*)d_in[6];
    float* out = (float*)d_out;

    cudaFuncSetAttribute(qkv_tc_kernel,   cudaFuncAttributeMaxDynamicSharedMemorySize, GEMM_SMEM_SZ);
    cudaFuncSetAttribute(proj_tc_kernel,  cudaFuncAttributeMaxDynamicSharedMemorySize, GEMM_SMEM_SZ);
    cudaFuncSetAttribute(attn_mma_kernel, cudaFuncAttributeMaxDynamicSharedMemorySize, ATT_SMEM);

    groupnorm_kernel<<<B_ * GROUPS, 256>>>(x, norm_w, norm_b);
    split_w_kernel<<<(QKVW_ELEMS + PROJW_ELEMS + 255) / 256, 256>>>(qkv_w, proj_w);
    {
        dim3 grid(N_ / 32, C_ / 32, B_);
        transX_kernel<<<grid, 256>>>();
    }
    {   // QKV GEMM + fused Q/K/V conversion
        dim3 grid(N_ / 128, (3 * C_) / 128, B_);
        qkv_tc_kernel<<<grid, 256, GEMM_SMEM_SZ>>>(qkv_b);
    }
    {   // flash attention (tensor), qtile 64
        dim3 grid(N_ / 64, HEADS, B_);
        attn_mma_kernel<<<grid, 128, ATT_SMEM>>>();
    }
    {   // proj + bias + residual -> out
        dim3 grid(N_ / 128, C_ / 128, B_);
        proj_tc_kernel<<<grid, 256, GEMM_SMEM_SZ>>>(proj_b, x, out);
    }
}